// round 7
// baseline (speedup 1.0000x reference)
#include <cuda_runtime.h>

// ---------------- scratch (device globals; no allocation) ----------------
__device__ __align__(16) float g_h2[64*51*14*14];     // pool1 out [64,51,14,14]
__device__ __align__(16) float g_h3[64*255*10*10];    // dw2 out   [64,255,10,10]
__device__ __align__(16) float g_h4t[64*25*528];      // pool2 out TRANSPOSED [b][pos][ch], pad 528
__device__ __align__(16) float g_wpad[100*528];       // oo_w padded [100][528]
__device__ __align__(16) float g_part[24*64*100*25];  // oo split-K partials
__device__ __align__(16) float g_h5[64*100*25];       // oo out (post relu)
__device__ __align__(16) float g_f1[64*120];          // fc1 out

// =======================================================================
// fuse1: dw1 + pc1 + relu + maxpool. grid (64 b, 2 halves), 256 thr.
// Prologue also pads oo_w -> g_wpad and zeroes g_h4t pad columns.
// =======================================================================
__global__ __launch_bounds__(256) void k_fuse1(
    const float* __restrict__ x, const float* __restrict__ dw1w,
    const float* __restrict__ dw1b, const float* __restrict__ pc1w,
    const float* __restrict__ pc1b, const float* __restrict__ oo_w) {
    extern __shared__ float sm[];
    float* xs  = sm;            // 3*32*33 = 3168
    float* h1  = xs + 3168;     // 18*14*28 = 7056
    float* ws  = h1 + 7056;     // 450
    float* wb  = ws + 450;      // 18
    float* pwv = wb + 18;       // 153
    float* pbs = pwv + 153;     // 51
    int*   sidx = (int*)(pbs + 51); // 51*3

    int b = blockIdx.x, sy = blockIdx.y, tid = threadIdx.x;

    // ---- global prep work distributed over all 128 blocks ----
    {
        int gid = (blockIdx.y*64 + blockIdx.x)*256 + tid;   // 0..32767
        for (int i = gid; i < 52800; i += 32768) {          // g_wpad [100][528]
            int o = i / 528, c = i - o*528;
            g_wpad[i] = (c < 515) ? oo_w[o*515 + c] : 0.f;
        }
        for (int i = gid; i < 20800; i += 32768) {          // g_h4t pad cols 515..527
            int row = i / 13, e = i - row*13;
            g_h4t[row*528 + 515 + e] = 0.f;
        }
    }

    for (int i = tid; i < 3072; i += 256) {
        int c = i >> 10, r = (i >> 5) & 31, col = i & 31;
        xs[c*1056 + r*33 + col] = x[(size_t)b*3072 + i];
    }
    for (int i = tid; i < 450; i += 256) ws[i] = dw1w[i];
    if (tid < 18) wb[tid] = dw1b[tid];
    if (tid < 153) pwv[tid] = pc1w[tid];
    if (tid < 51) {
        pbs[tid] = pc1b[tid];
        int g = tid, gi = g, i = 0;
        for (;;) { int cv = (6 - i) + 2 * (5 - i); if (gi < cv) break; gi -= cv; i++; }
        int j, k;
        if (gi < 6 - i) { j = 0; k = i + gi; }
        else { gi -= 6 - i; int pj = 5 - i; j = 1 + gi / pj; k = i + 1 + gi % pj; }
        sidx[g*3+0] = (0==j) ? i*3+0 : k*3+0;
        sidx[g*3+1] = (1==j) ? i*3+1 : k*3+1;
        sidx[g*3+2] = (2==j) ? i*3+2 : k*3+2;
    }
    __syncthreads();

    // dw1: tasks = (o, py_l 0..13, quarter) = 1008; each computes 7 px.
    for (int t = tid; t < 1008; t += 256) {
        int o = t / 56, r = t % 56, py_l = r / 4, q = r % 4, x0 = q * 7;
        int py = sy*14 + py_l;
        int c = o / 6;
        const float* xb = &xs[c*1056 + py*33 + x0];
        float win[5][11];
        #pragma unroll
        for (int dy = 0; dy < 5; dy++)
            #pragma unroll
            for (int dx = 0; dx < 11; dx++) win[dy][dx] = xb[dy*33 + dx];
        float bv = wb[o];
        float acc[7];
        #pragma unroll
        for (int u = 0; u < 7; u++) acc[u] = bv;
        #pragma unroll
        for (int dy = 0; dy < 5; dy++)
            #pragma unroll
            for (int dx = 0; dx < 5; dx++) {
                float wv = ws[o*25 + dy*5 + dx];
                #pragma unroll
                for (int u = 0; u < 7; u++) acc[u] = fmaf(win[dy][dx+u], wv, acc[u]);
            }
        #pragma unroll
        for (int u = 0; u < 7; u++) h1[o*392 + py_l*28 + x0 + u] = acc[u];
    }
    __syncthreads();

    // pc1 + pool: tasks = (g, qy_l 0..6, qp 0..6) = 2499; 2 outputs each.
    for (int t = tid; t < 2499; t += 256) {
        int g = t / 49, r = t % 49, qy_l = r / 7, qp = r % 7;
        float w0 = pwv[g*3], w1 = pwv[g*3+1], w2 = pwv[g*3+2];
        int s0 = sidx[g*3], s1 = sidx[g*3+1], s2 = sidx[g*3+2];
        float v[2][4];
        #pragma unroll
        for (int dy = 0; dy < 2; dy++) {
            int base = (2*qy_l + dy)*28 + 4*qp;
            float2 a0 = *(const float2*)&h1[s0*392 + base];
            float2 a0b = *(const float2*)&h1[s0*392 + base + 2];
            float2 a1 = *(const float2*)&h1[s1*392 + base];
            float2 a1b = *(const float2*)&h1[s1*392 + base + 2];
            float2 a2 = *(const float2*)&h1[s2*392 + base];
            float2 a2b = *(const float2*)&h1[s2*392 + base + 2];
            v[dy][0] = fmaf(w0, a0.x,  fmaf(w1, a1.x,  w2*a2.x));
            v[dy][1] = fmaf(w0, a0.y,  fmaf(w1, a1.y,  w2*a2.y));
            v[dy][2] = fmaf(w0, a0b.x, fmaf(w1, a1b.x, w2*a2b.x));
            v[dy][3] = fmaf(w0, a0b.y, fmaf(w1, a1b.y, w2*a2b.y));
        }
        float bv = pbs[g];
        float o0 = fmaxf(fmaxf(v[0][0], v[0][1]), fmaxf(v[1][0], v[1][1]));
        float o1 = fmaxf(fmaxf(v[0][2], v[0][3]), fmaxf(v[1][2], v[1][3]));
        float* op = &g_h2[((size_t)b*51 + g)*196 + (sy*7 + qy_l)*14 + 2*qp];
        op[0] = fmaxf(o0 + bv, 0.f);
        op[1] = fmaxf(o1 + bv, 0.f);
    }
}

// =======================================================================
// dw2: [64,51,14,14] -> [64,255,10,10].
// =======================================================================
__global__ __launch_bounds__(256) void k_dw2(const float* __restrict__ w,
                                             const float* __restrict__ bias) {
    __shared__ float xs[7*196];
    int bx = blockIdx.x, b = blockIdx.y, tid = threadIdx.x;
    int t0 = bx * 256;
    int c0 = t0 / 50;
    int c1 = min((t0 + 255) / 50, 50);
    int nch = c1 - c0 + 1;
    for (int i = tid; i < nch*196; i += 256)
        xs[i] = g_h2[((size_t)b*51 + c0)*196 + i];
    __syncthreads();

    int t = t0 + tid;
    if (t >= 2550) return;
    int o = t / 10, py = t % 10;
    int cl = o / 5 - c0;
    float wr[25];
    #pragma unroll
    for (int i = 0; i < 25; i++) wr[i] = __ldg(&w[o*25 + i]);
    float bv = __ldg(&bias[o]);
    const float* ib = &xs[cl*196 + py*14];
    float* outp = &g_h3[((size_t)b*255 + o)*100 + py*10];
    #pragma unroll
    for (int h = 0; h < 2; h++) {
        int px0 = h * 5;
        float win[5][9];
        #pragma unroll
        for (int dy = 0; dy < 5; dy++)
            #pragma unroll
            for (int dx = 0; dx < 9; dx++) win[dy][dx] = ib[dy*14 + px0 + dx];
        float acc[5] = {bv, bv, bv, bv, bv};
        #pragma unroll
        for (int dy = 0; dy < 5; dy++)
            #pragma unroll
            for (int dx = 0; dx < 5; dx++) {
                float wv = wr[dy*5 + dx];
                #pragma unroll
                for (int u = 0; u < 5; u++) acc[u] = fmaf(win[dy][dx+u], wv, acc[u]);
            }
        #pragma unroll
        for (int u = 0; u < 5; u++) outp[px0 + u] = acc[u];
    }
}

// =======================================================================
// pc2 + relu + maxpool -> g_h4t [b][pos][528] (transposed, padded).
// =======================================================================
__device__ __constant__ int c_bk[11]   = {0,1,2,2,3,3,3,4,4,4,4};
__device__ __constant__ int c_bt[11]   = {0,0,0,52,0,52,104,0,52,104,156};
__device__ __constant__ int c_bc[11]   = {1,52,52,51,52,52,50,52,52,52,49};
__device__ __constant__ int c_base[5]  = {0,205,359,462,514};

__global__ __launch_bounds__(160) void k_pc2(const float* __restrict__ pw,
                                             const float* __restrict__ pb) {
    __shared__ __align__(16) float Xs[5100];
    __shared__ __align__(16) float Wt[51*52];
    __shared__ int   s_g[52], s_cc[52], s_j[52];
    __shared__ float s_b[52];
    int blk = blockIdx.x, b = blockIdx.y, tid = threadIdx.x;
    int k = c_bk[blk], ts = c_bt[blk], cnt = c_bc[blk];

    const float* xsrc = g_h3 + ((size_t)b*255 + k*51)*100;
    for (int i = tid; i < 5100; i += 160) Xs[i] = xsrc[i];
    if (tid < cnt) {
        int t = ts + tid;
        int i, j;
        if (t <= k) { i = t; j = 0; }
        else { int r = t - k - 1; i = r % k; j = 1 + r / k; }
        int g;
        if (j == 0) g = c_base[i] + (k - i);
        else        g = c_base[i] + (5 - i) + (j - 1)*(4 - i) + (k - i - 1);
        s_g[tid] = g; s_cc[tid] = i*51 + j; s_j[tid] = j; s_b[tid] = pb[g];
    }
    __syncthreads();
    for (int i = tid; i < cnt*51; i += 160) {
        int l = i / 51, c = i % 51;
        Wt[c*52 + l] = pw[s_g[l]*51 + c];
    }
    __syncthreads();

    int gt = tid / 5, rp = tid % 5;
    int l0 = gt * 2;
    if (tid >= 130 || l0 >= cnt) return;
    bool v1 = (l0 + 1 < cnt);
    int y0 = 2 * rp;

    float a0[20], a1[20];
    #pragma unroll
    for (int u = 0; u < 20; u++) { a0[u] = 0.f; a1[u] = 0.f; }

    #pragma unroll 3
    for (int c = 0; c < 51; c++) {
        float2 wp2 = *(const float2*)&Wt[c*52 + l0];
        const float4* xr = (const float4*)&Xs[c*100 + y0*10];
        #pragma unroll
        for (int q = 0; q < 5; q++) {
            float4 xv = xr[q];
            a0[4*q+0] = fmaf(wp2.x, xv.x, a0[4*q+0]);
            a0[4*q+1] = fmaf(wp2.x, xv.y, a0[4*q+1]);
            a0[4*q+2] = fmaf(wp2.x, xv.z, a0[4*q+2]);
            a0[4*q+3] = fmaf(wp2.x, xv.w, a0[4*q+3]);
            a1[4*q+0] = fmaf(wp2.y, xv.x, a1[4*q+0]);
            a1[4*q+1] = fmaf(wp2.y, xv.y, a1[4*q+1]);
            a1[4*q+2] = fmaf(wp2.y, xv.z, a1[4*q+2]);
            a1[4*q+3] = fmaf(wp2.y, xv.w, a1[4*q+3]);
        }
    }

    #pragma unroll
    for (int s = 0; s < 2; s++) {
        if (s == 1 && !v1) break;
        int l = l0 + s;
        float* a = (s == 0) ? a0 : a1;
        int jj = s_j[l], cc = s_cc[l];
        float wj = Wt[jj*52 + l];
        const float* gs = g_h3 + ((size_t)b*255 + cc)*100 + y0*10;
        const float* xj = &Xs[jj*100 + y0*10];
        #pragma unroll
        for (int u = 0; u < 20; u++)
            a[u] = fmaf(wj, gs[u] - xj[u], a[u]);
        float bv = s_b[l];
        // transposed store: g_h4t[b][rp*5+p][g]
        float* op = &g_h4t[((size_t)b*25 + rp*5)*528 + s_g[l]];
        #pragma unroll
        for (int p = 0; p < 5; p++) {
            float v = fmaxf(fmaxf(a[2*p], a[2*p+1]), fmaxf(a[10+2*p], a[10+2*p+1]));
            op[p*528] = fmaxf(v + bv, 0.f);
        }
    }
}

// =======================================================================
// oo v7: 24-way split-K, bank-conflict-free. grid (24 ks, 64 b), 128 thr.
// Slice 22 (24*22 = 528 exact). W transposed in smem Wt[cc][100];
// X [p][22] (22*pt mod 32 all distinct -> conflict-free LDS.64).
// Thread tile 4o x 5p. Partials to g_part (bias folded at ks=0).
// =======================================================================
__global__ __launch_bounds__(128) void k_oo(const float* __restrict__ ob) {
    __shared__ __align__(16) float Xs[25*22];    // [p][cc], stride 22
    __shared__ __align__(16) float Wt[22*100];   // [cc][o], stride 100
    int ks = blockIdx.x, b = blockIdx.y, tid = threadIdx.x;
    int c0 = ks * 22;

    // X: contiguous rows from g_h4t (coalesced 22-float runs)
    const float* xsrc = g_h4t + (size_t)b*13200 + c0;
    #pragma unroll
    for (int i = tid; i < 550; i += 128) {
        int p = i / 22, cc = i - p*22;
        Xs[i] = xsrc[p*528 + cc];
    }
    // W: read [o][cc] runs coalesced, store transposed Wt[cc][o]
    const float* wsrc = g_wpad + c0;
    #pragma unroll
    for (int i = tid; i < 2200; i += 128) {
        int o = i / 22, cc = i - o*22;
        Wt[cc*100 + o] = wsrc[o*528 + cc];
    }
    __syncthreads();

    if (tid >= 125) return;
    int ot = tid / 5, pt = tid - ot*5;
    int o0 = ot * 4;
    float acc[4][5];
    #pragma unroll
    for (int r = 0; r < 4; r++)
        #pragma unroll
        for (int kk = 0; kk < 5; kk++) acc[r][kk] = 0.f;

    #pragma unroll
    for (int c = 0; c < 22; c += 2) {
        float4 wA = *(const float4*)&Wt[c*100 + o0];        // 4 o's, col c
        float4 wB = *(const float4*)&Wt[(c+1)*100 + o0];    // 4 o's, col c+1
        float2 xv[5];
        #pragma unroll
        for (int kk = 0; kk < 5; kk++)
            xv[kk] = *(const float2*)&Xs[(pt + 5*kk)*22 + c];
        #pragma unroll
        for (int kk = 0; kk < 5; kk++) {
            acc[0][kk] = fmaf(wA.x, xv[kk].x, acc[0][kk]);
            acc[1][kk] = fmaf(wA.y, xv[kk].x, acc[1][kk]);
            acc[2][kk] = fmaf(wA.z, xv[kk].x, acc[2][kk]);
            acc[3][kk] = fmaf(wA.w, xv[kk].x, acc[3][kk]);
            acc[0][kk] = fmaf(wB.x, xv[kk].y, acc[0][kk]);
            acc[1][kk] = fmaf(wB.y, xv[kk].y, acc[1][kk]);
            acc[2][kk] = fmaf(wB.z, xv[kk].y, acc[2][kk]);
            acc[3][kk] = fmaf(wB.w, xv[kk].y, acc[3][kk]);
        }
    }

    float* op = &g_part[(((size_t)ks*64 + b)*100 + o0)*25];
    #pragma unroll
    for (int r = 0; r < 4; r++) {
        float bias = (ks == 0) ? __ldg(&ob[o0 + r]) : 0.f;
        #pragma unroll
        for (int kk = 0; kk < 5; kk++)
            op[r*25 + pt + 5*kk] = acc[r][kk] + bias;
    }
}

// =======================================================================
// reduce oo partials (24-way) + relu -> g_h5, float4
// =======================================================================
__global__ __launch_bounds__(256) void k_red() {
    int idx = blockIdx.x*256 + threadIdx.x;     // 40000 float4 total
    if (idx >= 40000) return;
    const float4* gp = (const float4*)g_part;
    float4 v = gp[idx];
    #pragma unroll
    for (int s = 1; s < 24; s++) {
        float4 u = gp[s*40000 + idx];
        v.x += u.x; v.y += u.y; v.z += u.z; v.w += u.w;
    }
    ((float4*)g_h5)[idx] = make_float4(fmaxf(v.x,0.f), fmaxf(v.y,0.f),
                                       fmaxf(v.z,0.f), fmaxf(v.w,0.f));
}

// =======================================================================
// fc1: [64,2500]x[2500,120] -> g_f1 (+bias+relu).
// grid (15 o-tiles x 8o, 16 b-tiles x 4b), 256 thr, split-K(8), dbl-buffered.
// =======================================================================
__global__ __launch_bounds__(256) void k_fc1(const float* __restrict__ w1,
                                             const float* __restrict__ b1) {
    __shared__ __align__(16) float Xs[2][4*260];
    __shared__ __align__(16) float Ws2[2][8*260];
    __shared__ float s_red[256];
    int o0 = blockIdx.x * 8, b0 = blockIdx.y * 4, tid = threadIdx.x;
    int oi = tid & 7, bi = (tid >> 3) & 3, ksl = tid >> 5;

    #pragma unroll
    for (int u = 0; u < 4; u++) {
        int i = tid + u*256;
        int rw = i >> 8, cc = i & 255;
        Xs[0][rw*260 + cc] = g_h5[(size_t)(b0+rw)*2500 + cc];
    }
    #pragma unroll
    for (int u = 0; u < 8; u++) {
        int i = tid + u*256;
        int rw = i >> 8, cc = i & 255;
        Ws2[0][rw*260 + cc] = w1[(size_t)(o0+rw)*2500 + cc];
    }
    __syncthreads();

    float acc = 0.f;
    for (int ch = 0; ch < 10; ch++) {
        int cur = ch & 1;
        float xreg[4], wreg[8];
        if (ch < 9) {
            int cb = (ch + 1) * 256;
            #pragma unroll
            for (int u = 0; u < 4; u++) {
                int i = tid + u*256;
                int rw = i >> 8, cc = i & 255;
                int c = cb + cc;
                xreg[u] = (c < 2500) ? g_h5[(size_t)(b0+rw)*2500 + c] : 0.f;
            }
            #pragma unroll
            for (int u = 0; u < 8; u++) {
                int i = tid + u*256;
                int rw = i >> 8, cc = i & 255;
                int c = cb + cc;
                wreg[u] = (c < 2500) ? w1[(size_t)(o0+rw)*2500 + c] : 0.f;
            }
        }
        const float4* xp = (const float4*)&Xs[cur][bi*260 + ksl*32];
        const float4* wp = (const float4*)&Ws2[cur][oi*260 + ksl*32];
        #pragma unroll
        for (int q = 0; q < 8; q++) {
            float4 xv = xp[q], wv = wp[q];
            acc = fmaf(wv.x, xv.x, acc);
            acc = fmaf(wv.y, xv.y, acc);
            acc = fmaf(wv.z, xv.z, acc);
            acc = fmaf(wv.w, xv.w, acc);
        }
        if (ch < 9) {
            #pragma unroll
            for (int u = 0; u < 4; u++) {
                int i = tid + u*256;
                int rw = i >> 8, cc = i & 255;
                Xs[1-cur][rw*260 + cc] = xreg[u];
            }
            #pragma unroll
            for (int u = 0; u < 8; u++) {
                int i = tid + u*256;
                int rw = i >> 8, cc = i & 255;
                Ws2[1-cur][rw*260 + cc] = wreg[u];
            }
        }
        __syncthreads();
    }
    s_red[tid] = acc;
    __syncthreads();
    if (tid < 32) {
        float s = 0.f;
        #pragma unroll
        for (int u = 0; u < 8; u++) s += s_red[tid + 32*u];
        int o = o0 + (tid & 7), bb = b0 + (tid >> 3);
        g_f1[bb*120 + o] = fmaxf(s + __ldg(&b1[o]), 0.f);
    }
}

// =======================================================================
// fc2 + fc3: [64,120] -> 84 -> 10
// =======================================================================
__global__ __launch_bounds__(128) void k_fc23(
    const float* __restrict__ w2, const float* __restrict__ b2,
    const float* __restrict__ w3, const float* __restrict__ b3,
    float* __restrict__ out) {
    __shared__ __align__(16) float sf1[120];
    __shared__ __align__(16) float sf2[84];
    int b = blockIdx.x, tid = threadIdx.x;
    if (tid < 120) sf1[tid] = g_f1[b*120 + tid];
    __syncthreads();
    if (tid < 84) {
        const float4* wp = (const float4*)(w2 + tid*120);
        const float4* xp = (const float4*)sf1;
        float s = 0.f;
        #pragma unroll
        for (int q = 0; q < 30; q++) {
            float4 wv = wp[q], xv = xp[q];
            s = fmaf(wv.x, xv.x, s); s = fmaf(wv.y, xv.y, s);
            s = fmaf(wv.z, xv.z, s); s = fmaf(wv.w, xv.w, s);
        }
        sf2[tid] = fmaxf(s + b2[tid], 0.f);
    }
    __syncthreads();
    if (tid < 10) {
        const float4* wp = (const float4*)(w3 + tid*84);
        const float4* xp = (const float4*)sf2;
        float s = 0.f;
        #pragma unroll
        for (int q = 0; q < 21; q++) {
            float4 wv = wp[q], xv = xp[q];
            s = fmaf(wv.x, xv.x, s); s = fmaf(wv.y, xv.y, s);
            s = fmaf(wv.z, xv.z, s); s = fmaf(wv.w, xv.w, s);
        }
        out[b*10 + tid] = s + b3[tid];
    }
}

// ---------------- launch ----------------
extern "C" void kernel_launch(void* const* d_in, const int* in_sizes, int n_in,
                              void* d_out, int out_size) {
    const float* x      = (const float*)d_in[0];
    const float* dw1_w  = (const float*)d_in[1];
    const float* dw1_b  = (const float*)d_in[2];
    const float* pc1_w  = (const float*)d_in[3];
    const float* pc1_b  = (const float*)d_in[4];
    const float* dw2_w  = (const float*)d_in[5];
    const float* dw2_b  = (const float*)d_in[6];
    const float* pc2_w  = (const float*)d_in[7];
    const float* pc2_b  = (const float*)d_in[8];
    const float* oo_w   = (const float*)d_in[9];
    const float* oo_b   = (const float*)d_in[10];
    const float* fc1_w  = (const float*)d_in[11];
    const float* fc1_b  = (const float*)d_in[12];
    const float* fc2_w  = (const float*)d_in[13];
    const float* fc2_b  = (const float*)d_in[14];
    const float* fc3_w  = (const float*)d_in[15];
    const float* fc3_b  = (const float*)d_in[16];
    float* out = (float*)d_out;

    static bool attr_done = false;
    const int fuse1_smem = (3168 + 7056 + 450 + 18 + 153 + 51 + 153) * 4 + 16;
    if (!attr_done) {
        cudaFuncSetAttribute(k_fuse1, cudaFuncAttributeMaxDynamicSharedMemorySize, fuse1_smem);
        attr_done = true;
    }

    k_fuse1<<<dim3(64, 2), 256, fuse1_smem>>>(x, dw1_w, dw1_b, pc1_w, pc1_b, oo_w);
    k_dw2<<<dim3(10, 64), 256>>>(dw2_w, dw2_b);
    k_pc2<<<dim3(11, 64), 160>>>(pc2_w, pc2_b);
    k_oo<<<dim3(24, 64), 128>>>(oo_b);
    k_red<<<157, 256>>>();
    k_fc1<<<dim3(15, 16), 256>>>(fc1_w, fc1_b);
    k_fc23<<<64, 128>>>(fc2_w, fc2_b, fc3_w, fc3_b, out);
}

// round 9
// speedup vs baseline: 1.1152x; 1.1152x over previous
#include <cuda_runtime.h>

// ---------------- scratch (device globals; no allocation) ----------------
__device__ __align__(16) float g_h2[64*51*14*14];     // pool1 out [64,51,14,14]
__device__ __align__(16) float g_h3[64*255*10*10];    // dw2 out   [64,255,10,10]
__device__ __align__(16) float g_h4t[64*25*528];      // pool2 out TRANSPOSED [b][pos][ch]
__device__ __align__(16) float g_wpadT[528*100];      // oo_w transposed+padded [ch][o]
__device__ __align__(16) float g_part[12*64*25*100];  // oo split-K partials [ks][b][p][o]
__device__ __align__(16) float g_h5[64*100*25];       // oo out (post relu) [b][o][p]
__device__ __align__(16) float g_f1[64*120];          // fc1 out

// =======================================================================
// fuse1: dw1 + pc1 + relu + maxpool. grid (64 b, 7 y-slices), 256 thr.
// Slice sy: dw1 rows [4sy,4sy+4), pooled rows [2sy,2sy+2), x rows [4sy,4sy+8).
// Prologue builds g_wpadT (oo_w transposed) and zeroes g_h4t pad columns.
// =======================================================================
__global__ __launch_bounds__(256) void k_fuse1(
    const float* __restrict__ x, const float* __restrict__ dw1w,
    const float* __restrict__ dw1b, const float* __restrict__ pc1w,
    const float* __restrict__ pc1b, const float* __restrict__ oo_w) {
    __shared__ __align__(16) float xs[3*8*33];   // 792
    __shared__ __align__(16) float h1[18*4*28];  // 2016
    __shared__ float ws[450];
    __shared__ float wb[18];
    __shared__ float pwv[153];
    __shared__ float pbs[51];
    __shared__ int   sidx[153];

    int b = blockIdx.x, sy = blockIdx.y, tid = threadIdx.x;

    // ---- global prep distributed over 448 blocks * 256 thr = 114688 ----
    {
        int gid = (blockIdx.y*64 + blockIdx.x)*256 + tid;
        if (gid < 52800) {                       // g_wpadT [528][100]
            int c = gid / 100, o = gid - c*100;
            g_wpadT[gid] = (c < 515) ? oo_w[o*515 + c] : 0.f;
        }
        int gid2 = gid - 52800;
        if (gid2 >= 0 && gid2 < 20800) {         // g_h4t pad cols 515..527
            int row = gid2 / 13, e = gid2 - row*13;
            g_h4t[row*528 + 515 + e] = 0.f;
        }
    }

    // x rows [4sy, 4sy+8) for 3 channels
    for (int i = tid; i < 768; i += 256) {
        int c = i >> 8, r = (i >> 5) & 7, col = i & 31;
        xs[c*264 + r*33 + col] = x[(size_t)b*3072 + c*1024 + (4*sy + r)*32 + col];
    }
    for (int i = tid; i < 450; i += 256) ws[i] = dw1w[i];
    if (tid < 18) wb[tid] = dw1b[tid];
    if (tid < 153) pwv[tid] = pc1w[tid];
    if (tid < 51) {
        pbs[tid] = pc1b[tid];
        int g = tid, gi = g, i = 0;
        for (;;) { int cv = (6 - i) + 2 * (5 - i); if (gi < cv) break; gi -= cv; i++; }
        int j, k;
        if (gi < 6 - i) { j = 0; k = i + gi; }
        else { gi -= 6 - i; int pj = 5 - i; j = 1 + gi / pj; k = i + 1 + gi % pj; }
        sidx[g*3+0] = (0==j) ? i*3+0 : k*3+0;
        sidx[g*3+1] = (1==j) ? i*3+1 : k*3+1;
        sidx[g*3+2] = (2==j) ? i*3+2 : k*3+2;
    }
    __syncthreads();

    // dw1: tasks = (o, py_l 0..3, quarter) = 288; each computes 7 px.
    for (int t = tid; t < 288; t += 256) {
        int o = t / 16, r = t % 16, py_l = r / 4, q = r % 4, x0 = q * 7;
        int c = o / 6;
        const float* xb = &xs[c*264 + py_l*33 + x0];
        float win[5][11];
        #pragma unroll
        for (int dy = 0; dy < 5; dy++)
            #pragma unroll
            for (int dx = 0; dx < 11; dx++) win[dy][dx] = xb[dy*33 + dx];
        float bv = wb[o];
        float acc[7];
        #pragma unroll
        for (int u = 0; u < 7; u++) acc[u] = bv;
        #pragma unroll
        for (int dy = 0; dy < 5; dy++)
            #pragma unroll
            for (int dx = 0; dx < 5; dx++) {
                float wv = ws[o*25 + dy*5 + dx];
                #pragma unroll
                for (int u = 0; u < 7; u++) acc[u] = fmaf(win[dy][dx+u], wv, acc[u]);
            }
        #pragma unroll
        for (int u = 0; u < 7; u++) h1[o*112 + py_l*28 + x0 + u] = acc[u];
    }
    __syncthreads();

    // pc1 + pool: tasks = (g, qy_l 0..1, qp 0..6) = 714; 2 outputs each.
    for (int t = tid; t < 714; t += 256) {
        int g = t / 14, r = t % 14, qy_l = r / 7, qp = r % 7;
        float w0 = pwv[g*3], w1 = pwv[g*3+1], w2 = pwv[g*3+2];
        int s0 = sidx[g*3], s1 = sidx[g*3+1], s2 = sidx[g*3+2];
        float v[2][4];
        #pragma unroll
        for (int dy = 0; dy < 2; dy++) {
            int base = (2*qy_l + dy)*28 + 4*qp;
            float2 a0 = *(const float2*)&h1[s0*112 + base];
            float2 a0b = *(const float2*)&h1[s0*112 + base + 2];
            float2 a1 = *(const float2*)&h1[s1*112 + base];
            float2 a1b = *(const float2*)&h1[s1*112 + base + 2];
            float2 a2 = *(const float2*)&h1[s2*112 + base];
            float2 a2b = *(const float2*)&h1[s2*112 + base + 2];
            v[dy][0] = fmaf(w0, a0.x,  fmaf(w1, a1.x,  w2*a2.x));
            v[dy][1] = fmaf(w0, a0.y,  fmaf(w1, a1.y,  w2*a2.y));
            v[dy][2] = fmaf(w0, a0b.x, fmaf(w1, a1b.x, w2*a2b.x));
            v[dy][3] = fmaf(w0, a0b.y, fmaf(w1, a1b.y, w2*a2b.y));
        }
        float bv = pbs[g];
        float o0 = fmaxf(fmaxf(v[0][0], v[0][1]), fmaxf(v[1][0], v[1][1]));
        float o1 = fmaxf(fmaxf(v[0][2], v[0][3]), fmaxf(v[1][2], v[1][3]));
        float* op = &g_h2[((size_t)b*51 + g)*196 + (2*sy + qy_l)*14 + 2*qp];
        op[0] = fmaxf(o0 + bv, 0.f);
        op[1] = fmaxf(o1 + bv, 0.f);
    }
}

// =======================================================================
// dw2: [64,51,14,14] -> [64,255,10,10].
// =======================================================================
__global__ __launch_bounds__(256) void k_dw2(const float* __restrict__ w,
                                             const float* __restrict__ bias) {
    __shared__ float xs[7*196];
    int bx = blockIdx.x, b = blockIdx.y, tid = threadIdx.x;
    int t0 = bx * 256;
    int c0 = t0 / 50;
    int c1 = min((t0 + 255) / 50, 50);
    int nch = c1 - c0 + 1;
    for (int i = tid; i < nch*196; i += 256)
        xs[i] = g_h2[((size_t)b*51 + c0)*196 + i];
    __syncthreads();

    int t = t0 + tid;
    if (t >= 2550) return;
    int o = t / 10, py = t % 10;
    int cl = o / 5 - c0;
    float wr[25];
    #pragma unroll
    for (int i = 0; i < 25; i++) wr[i] = __ldg(&w[o*25 + i]);
    float bv = __ldg(&bias[o]);
    const float* ib = &xs[cl*196 + py*14];
    float* outp = &g_h3[((size_t)b*255 + o)*100 + py*10];
    #pragma unroll
    for (int h = 0; h < 2; h++) {
        int px0 = h * 5;
        float win[5][9];
        #pragma unroll
        for (int dy = 0; dy < 5; dy++)
            #pragma unroll
            for (int dx = 0; dx < 9; dx++) win[dy][dx] = ib[dy*14 + px0 + dx];
        float acc[5] = {bv, bv, bv, bv, bv};
        #pragma unroll
        for (int dy = 0; dy < 5; dy++)
            #pragma unroll
            for (int dx = 0; dx < 5; dx++) {
                float wv = wr[dy*5 + dx];
                #pragma unroll
                for (int u = 0; u < 5; u++) acc[u] = fmaf(win[dy][dx+u], wv, acc[u]);
            }
        #pragma unroll
        for (int u = 0; u < 5; u++) outp[px0 + u] = acc[u];
    }
}

// =======================================================================
// pc2 + relu + maxpool -> g_h4t [b][pos][528] (transposed, padded).
// =======================================================================
__device__ __constant__ int c_bk[11]   = {0,1,2,2,3,3,3,4,4,4,4};
__device__ __constant__ int c_bt[11]   = {0,0,0,52,0,52,104,0,52,104,156};
__device__ __constant__ int c_bc[11]   = {1,52,52,51,52,52,50,52,52,52,49};
__device__ __constant__ int c_base[5]  = {0,205,359,462,514};

__global__ __launch_bounds__(160) void k_pc2(const float* __restrict__ pw,
                                             const float* __restrict__ pb) {
    __shared__ __align__(16) float Xs[5100];
    __shared__ __align__(16) float Wt[51*52];
    __shared__ int   s_g[52], s_cc[52], s_j[52];
    __shared__ float s_b[52];
    int blk = blockIdx.x, b = blockIdx.y, tid = threadIdx.x;
    int k = c_bk[blk], ts = c_bt[blk], cnt = c_bc[blk];

    const float* xsrc = g_h3 + ((size_t)b*255 + k*51)*100;
    for (int i = tid; i < 5100; i += 160) Xs[i] = xsrc[i];
    if (tid < cnt) {
        int t = ts + tid;
        int i, j;
        if (t <= k) { i = t; j = 0; }
        else { int r = t - k - 1; i = r % k; j = 1 + r / k; }
        int g;
        if (j == 0) g = c_base[i] + (k - i);
        else        g = c_base[i] + (5 - i) + (j - 1)*(4 - i) + (k - i - 1);
        s_g[tid] = g; s_cc[tid] = i*51 + j; s_j[tid] = j; s_b[tid] = pb[g];
    }
    __syncthreads();
    for (int i = tid; i < cnt*51; i += 160) {
        int l = i / 51, c = i % 51;
        Wt[c*52 + l] = pw[s_g[l]*51 + c];
    }
    __syncthreads();

    int gt = tid / 5, rp = tid % 5;
    int l0 = gt * 2;
    if (tid >= 130 || l0 >= cnt) return;
    bool v1 = (l0 + 1 < cnt);
    int y0 = 2 * rp;

    float a0[20], a1[20];
    #pragma unroll
    for (int u = 0; u < 20; u++) { a0[u] = 0.f; a1[u] = 0.f; }

    #pragma unroll 3
    for (int c = 0; c < 51; c++) {
        float2 wp2 = *(const float2*)&Wt[c*52 + l0];
        const float4* xr = (const float4*)&Xs[c*100 + y0*10];
        #pragma unroll
        for (int q = 0; q < 5; q++) {
            float4 xv = xr[q];
            a0[4*q+0] = fmaf(wp2.x, xv.x, a0[4*q+0]);
            a0[4*q+1] = fmaf(wp2.x, xv.y, a0[4*q+1]);
            a0[4*q+2] = fmaf(wp2.x, xv.z, a0[4*q+2]);
            a0[4*q+3] = fmaf(wp2.x, xv.w, a0[4*q+3]);
            a1[4*q+0] = fmaf(wp2.y, xv.x, a1[4*q+0]);
            a1[4*q+1] = fmaf(wp2.y, xv.y, a1[4*q+1]);
            a1[4*q+2] = fmaf(wp2.y, xv.z, a1[4*q+2]);
            a1[4*q+3] = fmaf(wp2.y, xv.w, a1[4*q+3]);
        }
    }

    #pragma unroll
    for (int s = 0; s < 2; s++) {
        if (s == 1 && !v1) break;
        int l = l0 + s;
        float* a = (s == 0) ? a0 : a1;
        int jj = s_j[l], cc = s_cc[l];
        float wj = Wt[jj*52 + l];
        const float* gs = g_h3 + ((size_t)b*255 + cc)*100 + y0*10;
        const float* xj = &Xs[jj*100 + y0*10];
        #pragma unroll
        for (int u = 0; u < 20; u++)
            a[u] = fmaf(wj, gs[u] - xj[u], a[u]);
        float bv = s_b[l];
        float* op = &g_h4t[((size_t)b*25 + rp*5)*528 + s_g[l]];
        #pragma unroll
        for (int p = 0; p < 5; p++) {
            float v = fmaxf(fmaxf(a[2*p], a[2*p+1]), fmaxf(a[10+2*p], a[10+2*p+1]));
            op[p*528] = fmaxf(v + bv, 0.f);
        }
    }
}

// =======================================================================
// oo v9: 12-way split-K, fully conflict-free. grid (12 ks, 64 b), 128 thr.
// Slice 44. Wt[44][100] staged as a LINEAR copy from pre-transposed g_wpadT.
// Thread map ot = tid%25 (o-tile of 4, lanes contiguous), pt = tid/25.
// W LDS.128 lanes-consecutive; X loads broadcast. Stores STG.128 coalesced
// into g_part[ks][b][p][100].
// =======================================================================
__global__ __launch_bounds__(128) void k_oo(const float* __restrict__ ob) {
    __shared__ __align__(16) float Xs[25*44];     // [p][cc]
    __shared__ __align__(16) float Wt[44*100];    // [cc][o]
    int ks = blockIdx.x, b = blockIdx.y, tid = threadIdx.x;
    int c0 = ks * 44;

    const float* xsrc = g_h4t + (size_t)b*13200 + c0;
    #pragma unroll
    for (int i = tid; i < 1100; i += 128) {
        int p = i / 44, cc = i - p*44;
        Xs[i] = xsrc[p*528 + cc];
    }
    const float* wsrc = g_wpadT + c0*100;   // contiguous 4400 floats
    #pragma unroll
    for (int i = tid; i < 4400; i += 128) Wt[i] = wsrc[i];
    __syncthreads();

    if (tid >= 125) return;
    int pt = tid / 25, ot = tid - pt*25;    // const divisors
    int o0 = ot * 4;
    float acc[4][5];
    #pragma unroll
    for (int r = 0; r < 4; r++)
        #pragma unroll
        for (int kk = 0; kk < 5; kk++) acc[r][kk] = 0.f;

    #pragma unroll
    for (int c = 0; c < 44; c += 2) {
        float4 wA = *(const float4*)&Wt[c*100 + o0];
        float4 wB = *(const float4*)&Wt[(c+1)*100 + o0];
        float2 xv[5];
        #pragma unroll
        for (int kk = 0; kk < 5; kk++)
            xv[kk] = *(const float2*)&Xs[(pt + 5*kk)*44 + c];   // broadcast
        #pragma unroll
        for (int kk = 0; kk < 5; kk++) {
            acc[0][kk] = fmaf(wA.x, xv[kk].x, acc[0][kk]);
            acc[1][kk] = fmaf(wA.y, xv[kk].x, acc[1][kk]);
            acc[2][kk] = fmaf(wA.z, xv[kk].x, acc[2][kk]);
            acc[3][kk] = fmaf(wA.w, xv[kk].x, acc[3][kk]);
            acc[0][kk] = fmaf(wB.x, xv[kk].y, acc[0][kk]);
            acc[1][kk] = fmaf(wB.y, xv[kk].y, acc[1][kk]);
            acc[2][kk] = fmaf(wB.z, xv[kk].y, acc[2][kk]);
            acc[3][kk] = fmaf(wB.w, xv[kk].y, acc[3][kk]);
        }
    }

    // bias at ks==0; coalesced STG.128 into [ks][b][p][100]
    float4 bias = make_float4(0.f, 0.f, 0.f, 0.f);
    if (ks == 0) {
        bias.x = __ldg(&ob[o0]);     bias.y = __ldg(&ob[o0 + 1]);
        bias.z = __ldg(&ob[o0 + 2]); bias.w = __ldg(&ob[o0 + 3]);
    }
    float* opb = &g_part[((size_t)(ks*64 + b)*25)*100 + o0];
    #pragma unroll
    for (int kk = 0; kk < 5; kk++) {
        int p = pt + 5*kk;
        float4 v = make_float4(acc[0][kk] + bias.x, acc[1][kk] + bias.y,
                               acc[2][kk] + bias.z, acc[3][kk] + bias.w);
        *(float4*)&opb[p*100] = v;
    }
}

// =======================================================================
// reduce oo partials (12-way) + relu + transpose [p][o]->[o][p] -> g_h5.
// grid 64 (block per b), 256 thr.
// =======================================================================
__global__ __launch_bounds__(256) void k_red() {
    __shared__ float t[2500];
    int b = blockIdx.x, tid = threadIdx.x;
    float a[10];
    #pragma unroll
    for (int u = 0; u < 10; u++) {
        int i = u*256 + tid;
        float s = 0.f;
        if (i < 2500) {
            #pragma unroll
            for (int ss = 0; ss < 12; ss++)
                s += g_part[(size_t)(ss*64 + b)*2500 + i];
            t[i] = fmaxf(s, 0.f);
        }
        a[u] = s; (void)a;
    }
    __syncthreads();
    for (int j = tid; j < 2500; j += 256) {
        int o = j / 25, p = j - o*25;
        g_h5[(size_t)b*2500 + j] = t[p*100 + o];
    }
}

// =======================================================================
// fc1: [64,2500]x[2500,120] -> g_f1 (+bias+relu).
// grid (15 o-tiles x 8o, 16 b-tiles x 4b), 256 thr, split-K(8), dbl-buffered.
// =======================================================================
__global__ __launch_bounds__(256) void k_fc1(const float* __restrict__ w1,
                                             const float* __restrict__ b1) {
    __shared__ __align__(16) float Xs[2][4*260];
    __shared__ __align__(16) float Ws2[2][8*260];
    __shared__ float s_red[256];
    int o0 = blockIdx.x * 8, b0 = blockIdx.y * 4, tid = threadIdx.x;
    int oi = tid & 7, bi = (tid >> 3) & 3, ksl = tid >> 5;

    #pragma unroll
    for (int u = 0; u < 4; u++) {
        int i = tid + u*256;
        int rw = i >> 8, cc = i & 255;
        Xs[0][rw*260 + cc] = g_h5[(size_t)(b0+rw)*2500 + cc];
    }
    #pragma unroll
    for (int u = 0; u < 8; u++) {
        int i = tid + u*256;
        int rw = i >> 8, cc = i & 255;
        Ws2[0][rw*260 + cc] = w1[(size_t)(o0+rw)*2500 + cc];
    }
    __syncthreads();

    float acc = 0.f;
    for (int ch = 0; ch < 10; ch++) {
        int cur = ch & 1;
        float xreg[4], wreg[8];
        if (ch < 9) {
            int cb = (ch + 1) * 256;
            #pragma unroll
            for (int u = 0; u < 4; u++) {
                int i = tid + u*256;
                int rw = i >> 8, cc = i & 255;
                int c = cb + cc;
                xreg[u] = (c < 2500) ? g_h5[(size_t)(b0+rw)*2500 + c] : 0.f;
            }
            #pragma unroll
            for (int u = 0; u < 8; u++) {
                int i = tid + u*256;
                int rw = i >> 8, cc = i & 255;
                int c = cb + cc;
                wreg[u] = (c < 2500) ? w1[(size_t)(o0+rw)*2500 + c] : 0.f;
            }
        }
        const float4* xp = (const float4*)&Xs[cur][bi*260 + ksl*32];
        const float4* wp = (const float4*)&Ws2[cur][oi*260 + ksl*32];
        #pragma unroll
        for (int q = 0; q < 8; q++) {
            float4 xv = xp[q], wv = wp[q];
            acc = fmaf(wv.x, xv.x, acc);
            acc = fmaf(wv.y, xv.y, acc);
            acc = fmaf(wv.z, xv.z, acc);
            acc = fmaf(wv.w, xv.w, acc);
        }
        if (ch < 9) {
            #pragma unroll
            for (int u = 0; u < 4; u++) {
                int i = tid + u*256;
                int rw = i >> 8, cc = i & 255;
                Xs[1-cur][rw*260 + cc] = xreg[u];
            }
            #pragma unroll
            for (int u = 0; u < 8; u++) {
                int i = tid + u*256;
                int rw = i >> 8, cc = i & 255;
                Ws2[1-cur][rw*260 + cc] = wreg[u];
            }
        }
        __syncthreads();
    }
    s_red[tid] = acc;
    __syncthreads();
    if (tid < 32) {
        float s = 0.f;
        #pragma unroll
        for (int u = 0; u < 8; u++) s += s_red[tid + 32*u];
        int o = o0 + (tid & 7), bb = b0 + (tid >> 3);
        g_f1[bb*120 + o] = fmaxf(s + __ldg(&b1[o]), 0.f);
    }
}

// =======================================================================
// fc2 + fc3: [64,120] -> 84 -> 10
// =======================================================================
__global__ __launch_bounds__(128) void k_fc23(
    const float* __restrict__ w2, const float* __restrict__ b2,
    const float* __restrict__ w3, const float* __restrict__ b3,
    float* __restrict__ out) {
    __shared__ __align__(16) float sf1[120];
    __shared__ __align__(16) float sf2[84];
    int b = blockIdx.x, tid = threadIdx.x;
    if (tid < 120) sf1[tid] = g_f1[b*120 + tid];
    __syncthreads();
    if (tid < 84) {
        const float4* wp = (const float4*)(w2 + tid*120);
        const float4* xp = (const float4*)sf1;
        float s = 0.f;
        #pragma unroll
        for (int q = 0; q < 30; q++) {
            float4 wv = wp[q], xv = xp[q];
            s = fmaf(wv.x, xv.x, s); s = fmaf(wv.y, xv.y, s);
            s = fmaf(wv.z, xv.z, s); s = fmaf(wv.w, xv.w, s);
        }
        sf2[tid] = fmaxf(s + b2[tid], 0.f);
    }
    __syncthreads();
    if (tid < 10) {
        const float4* wp = (const float4*)(w3 + tid*84);
        const float4* xp = (const float4*)sf2;
        float s = 0.f;
        #pragma unroll
        for (int q = 0; q < 21; q++) {
            float4 wv = wp[q], xv = xp[q];
            s = fmaf(wv.x, xv.x, s); s = fmaf(wv.y, xv.y, s);
            s = fmaf(wv.z, xv.z, s); s = fmaf(wv.w, xv.w, s);
        }
        out[b*10 + tid] = s + b3[tid];
    }
}

// ---------------- launch ----------------
extern "C" void kernel_launch(void* const* d_in, const int* in_sizes, int n_in,
                              void* d_out, int out_size) {
    const float* x      = (const float*)d_in[0];
    const float* dw1_w  = (const float*)d_in[1];
    const float* dw1_b  = (const float*)d_in[2];
    const float* pc1_w  = (const float*)d_in[3];
    const float* pc1_b  = (const float*)d_in[4];
    const float* dw2_w  = (const float*)d_in[5];
    const float* dw2_b  = (const float*)d_in[6];
    const float* pc2_w  = (const float*)d_in[7];
    const float* pc2_b  = (const float*)d_in[8];
    const float* oo_w   = (const float*)d_in[9];
    const float* oo_b   = (const float*)d_in[10];
    const float* fc1_w  = (const float*)d_in[11];
    const float* fc1_b  = (const float*)d_in[12];
    const float* fc2_w  = (const float*)d_in[13];
    const float* fc2_b  = (const float*)d_in[14];
    const float* fc3_w  = (const float*)d_in[15];
    const float* fc3_b  = (const float*)d_in[16];
    float* out = (float*)d_out;

    k_fuse1<<<dim3(64, 7), 256>>>(x, dw1_w, dw1_b, pc1_w, pc1_b, oo_w);
    k_dw2<<<dim3(10, 64), 256>>>(dw2_w, dw2_b);
    k_pc2<<<dim3(11, 64), 160>>>(pc2_w, pc2_b);
    k_oo<<<dim3(12, 64), 128>>>(oo_b);
    k_red<<<64, 256>>>();
    k_fc1<<<dim3(15, 16), 256>>>(fc1_w, fc1_b);
    k_fc23<<<64, 128>>>(fc2_w, fc2_b, fc3_w, fc3_b, out);
}